// round 15
// baseline (speedup 1.0000x reference)
#include <cuda_runtime.h>
#include <cuda_bf16.h>
#include <cstdint>

#define D 128
constexpr int MAXN = 50048;          // 391 * 128 exactly
constexpr int MAXE = 1000192;

// ---------------- scratch (static device globals; no allocation) ----------------
__device__ float4 g_dinv4[2 * MAXN];      // per layer: (d0, d1, d2, -) per node
__device__ int    g_count[MAXN];
__device__ int    g_rowstart[MAXN + 1];
__device__ int    g_cursor[MAXN];
__device__ float4 g_eff4 [MAXE];          // (e0, e1, e2, sid-as-int-bits) at CSR position
__device__ float  g_act0 [MAXN * D];      // channel 0 (tf32-rounded fp32); also layer-1 gather source
__device__ float  g_agg  [3 * MAXN * D];  // [c][MAXN][D] tf32-rounded aggregates
__device__ float  g_Bt   [2 * 4 * D * D]; // weights transposed [l][c][n][k], tf32-rounded
__device__ int    g_blksum[256];

__device__ __forceinline__ uint32_t f2tf32(float v) {
    uint32_t u;
    asm("cvt.rna.tf32.f32 %0, %1;" : "=r"(u) : "f"(v));
    return u;
}

// ---------------- init: count = 0 ----------------
__global__ void k_init(int N) {
    int i = blockIdx.x * blockDim.x + threadIdx.x;
    if (i < N) g_count[i] = 0;
}

// ---------------- edge pass 1: target histogram only ----------------
__global__ void k_edge1(const int* __restrict__ ei, int N, int E) {
    int e = blockIdx.x * blockDim.x + threadIdx.x;
    if (e >= E) return;
    atomicAdd(&g_count[ei[E + e]], 1);
}

// ---------------- block scans (2-pass) ----------------
__device__ __forceinline__ int block_incl_scan(int v, int* s) {
    int tid = threadIdx.x;
    s[tid] = v;
    __syncthreads();
    #pragma unroll
    for (int o = 1; o < 256; o <<= 1) {
        int t = (tid >= o) ? s[tid - o] : 0;
        __syncthreads();
        s[tid] += t;
        __syncthreads();
    }
    return s[tid];
}

__global__ void k_scan1(int N) {
    __shared__ int s[256];
    int i = blockIdx.x * 256 + threadIdx.x;
    int v = (i < N) ? g_count[i] : 0;
    block_incl_scan(v, s);
    if (threadIdx.x == 255) g_blksum[blockIdx.x] = s[255];
}

__global__ void k_scan3(int N, int E) {
    __shared__ int sb[256];
    __shared__ int s[256];
    int bid = blockIdx.x;
    int i = bid * 256 + threadIdx.x;
    int bv = g_blksum[threadIdx.x];
    block_incl_scan(bv, sb);
    int boff = (bid > 0) ? sb[bid - 1] : 0;
    int v = (i < N) ? g_count[i] : 0;
    int inc = block_incl_scan(v, s);
    if (i < N) {
        int excl = inc - v + boff;
        g_rowstart[i] = excl;
        g_cursor[i] = excl;
    }
    if (i == 0) g_rowstart[N] = E;
}

// ---------------- edge pass 2: scatter into CSR slots ----------------
__global__ void k_edge2(const int* __restrict__ ei,
                        const float* __restrict__ asp, const float* __restrict__ actx,
                        const float* __restrict__ alat,
                        const float* __restrict__ wsp, const float* __restrict__ wctx,
                        const float* __restrict__ wlat, int N, int E) {
    int e = blockIdx.x * blockDim.x + threadIdx.x;
    if (e >= E) return;
    int t = ei[E + e];
    int s = ei[e];
    int p = atomicAdd(&g_cursor[t], 1);
    float4 v;
    v.x = asp[e]  * wsp[e];
    v.y = actx[e] * wctx[e];
    v.z = alat[e] * wlat[e];
    v.w = __int_as_float(s);
    g_eff4[p] = v;
}

// ---------------- degrees + dinv4 for all layers; warp per node ----------------
__global__ void k_degdinv(const float* __restrict__ deg_power, int L, int N) {
    int gw = (blockIdx.x * blockDim.x + threadIdx.x) >> 5;
    int lane = threadIdx.x & 31;
    if (gw >= N) return;
    int s = g_rowstart[gw], e = g_rowstart[gw + 1];
    float d0 = 0.f, d1 = 0.f, d2 = 0.f;
    for (int p = s + lane; p < e; p += 32) {
        float4 v = __ldg(&g_eff4[p]);
        d0 += v.x; d1 += v.y; d2 += v.z;
    }
    #pragma unroll
    for (int o = 16; o > 0; o >>= 1) {
        d0 += __shfl_xor_sync(0xffffffffu, d0, o);
        d1 += __shfl_xor_sync(0xffffffffu, d1, o);
        d2 += __shfl_xor_sync(0xffffffffu, d2, o);
    }
    if (lane == 0) {
        float deg0 = fmaxf(1.f + d0, 1e-6f);
        float deg1 = fmaxf(1.f + d1, 1e-6f);
        float deg2 = fmaxf(1.f + d2, 1e-6f);
        for (int l = 0; l < L; l++) {
            float4 o;
            o.x = powf(deg0, __ldg(&deg_power[l * 3 + 0]));
            o.y = powf(deg1, __ldg(&deg_power[l * 3 + 1]));
            o.z = powf(deg2, __ldg(&deg_power[l * 3 + 2]));
            o.w = 0.f;
            g_dinv4[l * MAXN + gw] = o;
        }
    }
}

// ---------------- prep: rounded x -> g_act0 + rounded transposed weights -> g_Bt ----------------
__global__ void k_prep(const float* __restrict__ x,
                       const float* __restrict__ Wself, const float* __restrict__ W3,
                       int L, int N) {
    int idx = blockIdx.x * blockDim.x + threadIdx.x;
    int nX = N * (D / 4);
    if (idx < nX) {
        float4 v = __ldg((const float4*)x + idx);
        uint4 t;
        t.x = f2tf32(v.x); t.y = f2tf32(v.y);
        t.z = f2tf32(v.z); t.w = f2tf32(v.w);
        *(uint4*)((uint32_t*)g_act0 + (size_t)idx * 4) = t;
    } else {
        int j = idx - nX;
        if (j >= L * 4 * D * D) return;
        int l  = j / (4 * D * D);
        int r  = j % (4 * D * D);
        int c  = r / (D * D);
        int nk = r % (D * D);
        int n  = nk >> 7;
        int k  = nk & 127;
        float v = (c == 0) ? Wself[l * D * D + k * D + n]
                           : W3[((l * 3) + (c - 1)) * D * D + k * D + n];
        ((uint32_t*)g_Bt)[j] = f2tf32(v);
    }
}

// ---------------- aggregate: PERSISTENT grid; warp strides over nodes ----------------
__global__ void __launch_bounds__(256)
k_agg(const float* __restrict__ x, int use_h, int layer, int N, int total_warps) {
    int warp0 = (blockIdx.x * blockDim.x + threadIdx.x) >> 5;
    int lane = threadIdx.x & 31;
    const float* __restrict__ X = use_h ? g_act0 : x;
    const float4* __restrict__ dinv = g_dinv4 + layer * MAXN;
    int fo = lane * 4;

    for (int gw = warp0; gw < N; gw += total_warps) {
        int s = g_rowstart[gw];
        int e = g_rowstart[gw + 1];

        float4 a0 = make_float4(0.f, 0.f, 0.f, 0.f);
        float4 a1 = make_float4(0.f, 0.f, 0.f, 0.f);
        float4 a2 = make_float4(0.f, 0.f, 0.f, 0.f);

        int p = s;
        for (; p + 4 <= e; p += 4) {
            float4 e0 = __ldg(&g_eff4[p]);
            float4 e1 = __ldg(&g_eff4[p + 1]);
            float4 e2 = __ldg(&g_eff4[p + 2]);
            float4 e3 = __ldg(&g_eff4[p + 3]);
            int s0 = __float_as_int(e0.w);
            int s1 = __float_as_int(e1.w);
            int s2 = __float_as_int(e2.w);
            int s3 = __float_as_int(e3.w);
            float4 d0 = __ldg(&dinv[s0]);
            float4 d1 = __ldg(&dinv[s1]);
            float4 d2 = __ldg(&dinv[s2]);
            float4 d3 = __ldg(&dinv[s3]);
            float4 x0 = __ldg((const float4*)(X + (size_t)s0 * D + fo));
            float4 x1 = __ldg((const float4*)(X + (size_t)s1 * D + fo));
            float4 x2 = __ldg((const float4*)(X + (size_t)s2 * D + fo));
            float4 x3 = __ldg((const float4*)(X + (size_t)s3 * D + fo));
            float m;
            m = e0.x * d0.x; a0.x = fmaf(m, x0.x, a0.x); a0.y = fmaf(m, x0.y, a0.y); a0.z = fmaf(m, x0.z, a0.z); a0.w = fmaf(m, x0.w, a0.w);
            m = e0.y * d0.y; a1.x = fmaf(m, x0.x, a1.x); a1.y = fmaf(m, x0.y, a1.y); a1.z = fmaf(m, x0.z, a1.z); a1.w = fmaf(m, x0.w, a1.w);
            m = e0.z * d0.z; a2.x = fmaf(m, x0.x, a2.x); a2.y = fmaf(m, x0.y, a2.y); a2.z = fmaf(m, x0.z, a2.z); a2.w = fmaf(m, x0.w, a2.w);
            m = e1.x * d1.x; a0.x = fmaf(m, x1.x, a0.x); a0.y = fmaf(m, x1.y, a0.y); a0.z = fmaf(m, x1.z, a0.z); a0.w = fmaf(m, x1.w, a0.w);
            m = e1.y * d1.y; a1.x = fmaf(m, x1.x, a1.x); a1.y = fmaf(m, x1.y, a1.y); a1.z = fmaf(m, x1.z, a1.z); a1.w = fmaf(m, x1.w, a1.w);
            m = e1.z * d1.z; a2.x = fmaf(m, x1.x, a2.x); a2.y = fmaf(m, x1.y, a2.y); a2.z = fmaf(m, x1.z, a2.z); a2.w = fmaf(m, x1.w, a2.w);
            m = e2.x * d2.x; a0.x = fmaf(m, x2.x, a0.x); a0.y = fmaf(m, x2.y, a0.y); a0.z = fmaf(m, x2.z, a0.z); a0.w = fmaf(m, x2.w, a0.w);
            m = e2.y * d2.y; a1.x = fmaf(m, x2.x, a1.x); a1.y = fmaf(m, x2.y, a1.y); a1.z = fmaf(m, x2.z, a1.z); a1.w = fmaf(m, x2.w, a1.w);
            m = e2.z * d2.z; a2.x = fmaf(m, x2.x, a2.x); a2.y = fmaf(m, x2.y, a2.y); a2.z = fmaf(m, x2.z, a2.z); a2.w = fmaf(m, x2.w, a2.w);
            m = e3.x * d3.x; a0.x = fmaf(m, x3.x, a0.x); a0.y = fmaf(m, x3.y, a0.y); a0.z = fmaf(m, x3.z, a0.z); a0.w = fmaf(m, x3.w, a0.w);
            m = e3.y * d3.y; a1.x = fmaf(m, x3.x, a1.x); a1.y = fmaf(m, x3.y, a1.y); a1.z = fmaf(m, x3.z, a1.z); a1.w = fmaf(m, x3.w, a1.w);
            m = e3.z * d3.z; a2.x = fmaf(m, x3.x, a2.x); a2.y = fmaf(m, x3.y, a2.y); a2.z = fmaf(m, x3.z, a2.z); a2.w = fmaf(m, x3.w, a2.w);
        }
        for (; p < e; p++) {
            float4 ef = __ldg(&g_eff4[p]);
            int sid = __float_as_int(ef.w);
            float4 dv = __ldg(&dinv[sid]);
            float4 xv = __ldg((const float4*)(X + (size_t)sid * D + fo));
            float m0 = ef.x * dv.x, m1 = ef.y * dv.y, m2 = ef.z * dv.z;
            a0.x = fmaf(m0, xv.x, a0.x); a0.y = fmaf(m0, xv.y, a0.y); a0.z = fmaf(m0, xv.z, a0.z); a0.w = fmaf(m0, xv.w, a0.w);
            a1.x = fmaf(m1, xv.x, a1.x); a1.y = fmaf(m1, xv.y, a1.y); a1.z = fmaf(m1, xv.z, a1.z); a1.w = fmaf(m1, xv.w, a1.w);
            a2.x = fmaf(m2, xv.x, a2.x); a2.y = fmaf(m2, xv.y, a2.y); a2.z = fmaf(m2, xv.z, a2.z); a2.w = fmaf(m2, xv.w, a2.w);
        }

        float4 dt = dinv[gw];
        uint4 t;
        t.x = f2tf32(a0.x * dt.x); t.y = f2tf32(a0.y * dt.x);
        t.z = f2tf32(a0.z * dt.x); t.w = f2tf32(a0.w * dt.x);
        *(uint4*)((uint32_t*)g_agg + (size_t)gw * D + fo) = t;
        t.x = f2tf32(a1.x * dt.y); t.y = f2tf32(a1.y * dt.y);
        t.z = f2tf32(a1.z * dt.y); t.w = f2tf32(a1.w * dt.y);
        *(uint4*)((uint32_t*)g_agg + (size_t)MAXN * D + (size_t)gw * D + fo) = t;
        t.x = f2tf32(a2.x * dt.z); t.y = f2tf32(a2.y * dt.z);
        t.z = f2tf32(a2.z * dt.z); t.w = f2tf32(a2.w * dt.z);
        *(uint4*)((uint32_t*)g_agg + 2 * (size_t)MAXN * D + (size_t)gw * D + fo) = t;
    }
}

// ---------------- TF32 GEMM with cp.async double-buffered staging + fused LN ----------------
constexpr int PP = 36;
constexpr int ABYTES = 128 * PP * 4;
constexpr int BUFB = 2 * ABYTES;
constexpr int SMEM_GEMM = 2 * BUFB;               // 73728

__device__ __forceinline__ void cp16(uint32_t dst, const void* src) {
    asm volatile("cp.async.cg.shared.global [%0], [%1], 16;" :: "r"(dst), "l"(src));
}
__device__ __forceinline__ void cp_commit() {
    asm volatile("cp.async.commit_group;" ::: "memory");
}
__device__ __forceinline__ void cp_wait1() {
    asm volatile("cp.async.wait_group 1;" ::: "memory");
}
__device__ __forceinline__ void cp_wait0() {
    asm volatile("cp.async.wait_group 0;" ::: "memory");
}

__device__ __forceinline__ void mma_tf32(float* d, const uint32_t* a, const uint32_t* b) {
    asm volatile("mma.sync.aligned.m16n8k8.row.col.f32.tf32.tf32.f32 "
        "{%0,%1,%2,%3}, {%4,%5,%6,%7}, {%8,%9}, {%0,%1,%2,%3};"
        : "+f"(d[0]), "+f"(d[1]), "+f"(d[2]), "+f"(d[3])
        : "r"(a[0]), "r"(a[1]), "r"(a[2]), "r"(a[3]), "r"(b[0]), "r"(b[1]));
}

__global__ void __launch_bounds__(256, 2)
k_gemm_mma(int layer, const float* __restrict__ bias,
           const float* __restrict__ lng, const float* __restrict__ lnb,
           float* __restrict__ dout, int last, int N) {
    extern __shared__ char smem[];
    uint32_t sbase = (uint32_t)__cvta_generic_to_shared(smem);

    int tid = threadIdx.x;
    int wid = tid >> 5;
    int lane = tid & 31;
    int group = lane >> 2;
    int tg = lane & 3;
    int warp_m = wid >> 2;
    int warp_n = wid & 3;
    int bm0 = blockIdx.x * 128;

    const uint32_t* BtL = (const uint32_t*)g_Bt + (size_t)layer * 4 * D * D;

    float acc[4][4][4];
    #pragma unroll
    for (int mt = 0; mt < 4; mt++)
        #pragma unroll
        for (int nt = 0; nt < 4; nt++)
            #pragma unroll
            for (int j = 0; j < 4; j++) acc[mt][nt][j] = 0.f;

    auto stage = [&](int chunk, int b) {
        int c = chunk >> 2;
        int koff = (chunk & 3) * 32;
        const float* Asrc = (c == 0) ? g_act0 : (g_agg + (size_t)(c - 1) * MAXN * D);
        const uint32_t* bsrc = BtL + c * D * D + koff;
        uint32_t a_s = sbase + b * BUFB;
        uint32_t b_s = a_s + ABYTES;
        #pragma unroll
        for (int i = 0; i < 4; i++) {
            int u = tid + i * 256;
            int row = u >> 3;
            int q = u & 7;
            cp16(a_s + (uint32_t)(row * PP + q * 4) * 4,
                 Asrc + (size_t)(bm0 + row) * D + koff + q * 4);
            cp16(b_s + (uint32_t)(row * PP + q * 4) * 4,
                 bsrc + (size_t)row * D + q * 4);
        }
    };

    stage(0, 0);
    cp_commit();

    for (int ch = 0; ch < 16; ch++) {
        if (ch < 15) {
            stage(ch + 1, (ch + 1) & 1);
            cp_commit();
            cp_wait1();
        } else {
            cp_wait0();
        }
        __syncthreads();

        const uint32_t* As = (const uint32_t*)(smem + (ch & 1) * BUFB);
        const uint32_t* Bs = (const uint32_t*)(smem + (ch & 1) * BUFB + ABYTES);

        #pragma unroll
        for (int s = 0; s < 4; s++) {
            int ks = s * 8;
            uint32_t bf[4][2];
            #pragma unroll
            for (int nt = 0; nt < 4; nt++) {
                int n0 = warp_n * 32 + nt * 8 + group;
                int o = n0 * PP + ks + tg;
                bf[nt][0] = Bs[o];
                bf[nt][1] = Bs[o + 4];
            }
            #pragma unroll
            for (int mt = 0; mt < 4; mt++) {
                int r0 = warp_m * 64 + mt * 16 + group;
                int o = r0 * PP + ks + tg;
                uint32_t af[4];
                af[0] = As[o];
                af[1] = As[o + 8 * PP];
                af[2] = As[o + 4];
                af[3] = As[o + 8 * PP + 4];
                #pragma unroll
                for (int nt = 0; nt < 4; nt++)
                    mma_tf32(acc[mt][nt], af, bf[nt]);
            }
        }
        __syncthreads();
    }

    // ---- add bias ----
    #pragma unroll
    for (int mt = 0; mt < 4; mt++)
        #pragma unroll
        for (int nt = 0; nt < 4; nt++) {
            int c0 = warp_n * 32 + nt * 8 + tg * 2;
            float b0 = bias[c0], b1 = bias[c0 + 1];
            acc[mt][nt][0] += b0; acc[mt][nt][1] += b1;
            acc[mt][nt][2] += b0; acc[mt][nt][3] += b1;
        }

    if (last) {
        #pragma unroll
        for (int mt = 0; mt < 4; mt++) {
            int r0 = bm0 + warp_m * 64 + mt * 16 + group;
            #pragma unroll
            for (int nt = 0; nt < 4; nt++) {
                int c0 = warp_n * 32 + nt * 8 + tg * 2;
                if (r0 < N)
                    *(float2*)(dout + (size_t)r0 * D + c0) = make_float2(acc[mt][nt][0], acc[mt][nt][1]);
                if (r0 + 8 < N)
                    *(float2*)(dout + (size_t)(r0 + 8) * D + c0) = make_float2(acc[mt][nt][2], acc[mt][nt][3]);
            }
        }
        return;
    }

    // ---- fused LayerNorm + ReLU -> tf32-rounded g_act0 (reuses staging smem) ----
    float* rsum = (float*)smem;
    float* rsq  = rsum + 512;

    #pragma unroll
    for (int mt = 0; mt < 4; mt++) {
        float slo = 0.f, shi = 0.f, qlo = 0.f, qhi = 0.f;
        #pragma unroll
        for (int nt = 0; nt < 4; nt++) {
            slo += acc[mt][nt][0] + acc[mt][nt][1];
            shi += acc[mt][nt][2] + acc[mt][nt][3];
            qlo += acc[mt][nt][0] * acc[mt][nt][0] + acc[mt][nt][1] * acc[mt][nt][1];
            qhi += acc[mt][nt][2] * acc[mt][nt][2] + acc[mt][nt][3] * acc[mt][nt][3];
        }
        #pragma unroll
        for (int o = 1; o < 4; o <<= 1) {
            slo += __shfl_xor_sync(0xffffffffu, slo, o);
            shi += __shfl_xor_sync(0xffffffffu, shi, o);
            qlo += __shfl_xor_sync(0xffffffffu, qlo, o);
            qhi += __shfl_xor_sync(0xffffffffu, qhi, o);
        }
        if (tg == 0) {
            int rl = warp_m * 64 + mt * 16 + group;
            rsum[rl * 4 + warp_n] = slo;
            rsq [rl * 4 + warp_n] = qlo;
            rsum[(rl + 8) * 4 + warp_n] = shi;
            rsq [(rl + 8) * 4 + warp_n] = qhi;
        }
    }
    __syncthreads();

    #pragma unroll
    for (int mt = 0; mt < 4; mt++) {
        int rl = warp_m * 64 + mt * 16 + group;
        float s0 = rsum[rl * 4 + 0] + rsum[rl * 4 + 1] + rsum[rl * 4 + 2] + rsum[rl * 4 + 3];
        float q0 = rsq [rl * 4 + 0] + rsq [rl * 4 + 1] + rsq [rl * 4 + 2] + rsq [rl * 4 + 3];
        float s1 = rsum[(rl + 8) * 4 + 0] + rsum[(rl + 8) * 4 + 1] + rsum[(rl + 8) * 4 + 2] + rsum[(rl + 8) * 4 + 3];
        float q1 = rsq [(rl + 8) * 4 + 0] + rsq [(rl + 8) * 4 + 1] + rsq [(rl + 8) * 4 + 2] + rsq [(rl + 8) * 4 + 3];
        float mu0 = s0 * (1.0f / 128.0f);
        float mu1 = s1 * (1.0f / 128.0f);
        float rs0 = rsqrtf(q0 * (1.0f / 128.0f) - mu0 * mu0 + 1e-5f);
        float rs1 = rsqrtf(q1 * (1.0f / 128.0f) - mu1 * mu1 + 1e-5f);
        int r0 = bm0 + rl;
        #pragma unroll
        for (int nt = 0; nt < 4; nt++) {
            int c0 = warp_n * 32 + nt * 8 + tg * 2;
            float gc0 = lng[c0], gc1 = lng[c0 + 1];
            float bc0 = lnb[c0], bc1 = lnb[c0 + 1];
            float y00 = fmaxf((acc[mt][nt][0] - mu0) * rs0 * gc0 + bc0, 0.f);
            float y01 = fmaxf((acc[mt][nt][1] - mu0) * rs0 * gc1 + bc1, 0.f);
            float y10 = fmaxf((acc[mt][nt][2] - mu1) * rs1 * gc0 + bc0, 0.f);
            float y11 = fmaxf((acc[mt][nt][3] - mu1) * rs1 * gc1 + bc1, 0.f);
            if (r0 < N) {
                uint2 t = make_uint2(f2tf32(y00), f2tf32(y01));
                *(uint2*)((uint32_t*)g_act0 + (size_t)r0 * D + c0) = t;
            }
            if (r0 + 8 < N) {
                uint2 t = make_uint2(f2tf32(y10), f2tf32(y11));
                *(uint2*)((uint32_t*)g_act0 + (size_t)(r0 + 8) * D + c0) = t;
            }
        }
    }
}

// ---------------- launch ----------------
extern "C" void kernel_launch(void* const* d_in, const int* in_sizes, int n_in,
                              void* d_out, int out_size) {
    const float* x    = (const float*)d_in[0];
    const int*   ei   = (const int*)d_in[1];
    const float* asp  = (const float*)d_in[2];
    const float* actx = (const float*)d_in[3];
    const float* alat = (const float*)d_in[4];
    const float* wsp  = (const float*)d_in[5];
    const float* wctx = (const float*)d_in[6];
    const float* wlat = (const float*)d_in[7];
    const float* W3   = (const float*)d_in[8];   // [L,3,D,D]
    const float* Wslf = (const float*)d_in[9];   // [L,D,D]
    const float* bias = (const float*)d_in[10];  // [L,D]
    const float* degp = (const float*)d_in[11];  // [L,3]
    const float* lng  = (const float*)d_in[12];
    const float* lnb  = (const float*)d_in[13];
    float* out = (float*)d_out;

    int N = in_sizes[0] / D;
    int E = in_sizes[2];
    int L = in_sizes[10] / D;
    int nblk = (N + 255) / 256;

    cudaFuncSetAttribute(k_gemm_mma, cudaFuncAttributeMaxDynamicSharedMemorySize, SMEM_GEMM);

    k_init<<<(N + 255) / 256, 256>>>(N);
    k_edge1<<<(E + 255) / 256, 256>>>(ei, N, E);
    k_scan1<<<nblk, 256>>>(N);
    k_scan3<<<nblk, 256>>>(N, E);
    k_edge2<<<(E + 255) / 256, 256>>>(ei, asp, actx, alat, wsp, wctx, wlat, N, E);
    k_degdinv<<<(N * 32 + 255) / 256, 256>>>(degp, L, N);
    int prep_total = N * (D / 4) + L * 4 * D * D;
    k_prep<<<(prep_total + 255) / 256, 256>>>(x, Wslf, W3, L, N);

    // persistent agg grid: 4 blocks per SM
    int agg_blocks = 592;
    int total_warps = agg_blocks * 8;

    int gemm_grid = (N + 127) / 128;
    for (int l = 0; l < L; l++) {
        int use_h = (l > 0) ? 1 : 0;
        int last = (l == L - 1) ? 1 : 0;
        k_agg<<<agg_blocks, 256>>>(x, use_h, l, N, total_warps);
        k_gemm_mma<<<gemm_grid, 256, SMEM_GEMM>>>(l, bias + l * D, lng, lnb, out, last, N);
    }
}

// round 16
// speedup vs baseline: 1.0512x; 1.0512x over previous
#include <cuda_runtime.h>
#include <cuda_bf16.h>
#include <cstdint>

#define D 128
constexpr int MAXN = 50048;          // 391 * 128 exactly
constexpr int MAXE = 1000192;

// ---------------- scratch (static device globals; no allocation) ----------------
__device__ float4 g_dinv4[2 * MAXN];      // per layer: (d0, d1, d2, -) per node
__device__ int    g_count[MAXN];
__device__ int    g_rowstart[MAXN + 1];
__device__ int    g_cursor[MAXN];
__device__ float4 g_eff4 [MAXE];          // (e0, e1, e2, sid-as-int-bits) at CSR position
__device__ float  g_act0 [MAXN * D];      // channel 0 (tf32-rounded fp32); also layer-1 gather source
__device__ float  g_agg  [3 * MAXN * D];  // [c][MAXN][D] tf32-rounded aggregates
__device__ float  g_Bt   [2 * 4 * D * D]; // weights transposed [l][c][n][k], tf32-rounded
__device__ int    g_blksum[256];

__device__ __forceinline__ uint32_t f2tf32(float v) {
    uint32_t u;
    asm("cvt.rna.tf32.f32 %0, %1;" : "=r"(u) : "f"(v));
    return u;
}

// ---------------- init: count = 0 ----------------
__global__ void k_init(int N) {
    int i = blockIdx.x * blockDim.x + threadIdx.x;
    if (i < N) g_count[i] = 0;
}

// ---------------- edge pass 1: target histogram, 4 edges/thread via int4 ----------------
__global__ void k_edge1(const int* __restrict__ ei, int N, int E) {
    int q = blockIdx.x * blockDim.x + threadIdx.x;   // quad index
    int base = q * 4;
    if (base + 4 <= E) {
        int4 t = __ldg((const int4*)(ei + E + base));
        atomicAdd(&g_count[t.x], 1);
        atomicAdd(&g_count[t.y], 1);
        atomicAdd(&g_count[t.z], 1);
        atomicAdd(&g_count[t.w], 1);
    } else {
        for (int e = base; e < E; e++)
            atomicAdd(&g_count[__ldg(&ei[E + e])], 1);
    }
}

// ---------------- block scans (2-pass) ----------------
__device__ __forceinline__ int block_incl_scan(int v, int* s) {
    int tid = threadIdx.x;
    s[tid] = v;
    __syncthreads();
    #pragma unroll
    for (int o = 1; o < 256; o <<= 1) {
        int t = (tid >= o) ? s[tid - o] : 0;
        __syncthreads();
        s[tid] += t;
        __syncthreads();
    }
    return s[tid];
}

__global__ void k_scan1(int N) {
    __shared__ int s[256];
    int i = blockIdx.x * 256 + threadIdx.x;
    int v = (i < N) ? g_count[i] : 0;
    block_incl_scan(v, s);
    if (threadIdx.x == 255) g_blksum[blockIdx.x] = s[255];
}

__global__ void k_scan3(int N, int E) {
    __shared__ int sb[256];
    __shared__ int s[256];
    int bid = blockIdx.x;
    int i = bid * 256 + threadIdx.x;
    int bv = g_blksum[threadIdx.x];
    block_incl_scan(bv, sb);
    int boff = (bid > 0) ? sb[bid - 1] : 0;
    int v = (i < N) ? g_count[i] : 0;
    int inc = block_incl_scan(v, s);
    if (i < N) {
        int excl = inc - v + boff;
        g_rowstart[i] = excl;
        g_cursor[i] = excl;
    }
    if (i == 0) g_rowstart[N] = E;
}

// ---------------- edge pass 2: scatter into CSR slots ----------------
__global__ void k_edge2(const int* __restrict__ ei,
                        const float* __restrict__ asp, const float* __restrict__ actx,
                        const float* __restrict__ alat,
                        const float* __restrict__ wsp, const float* __restrict__ wctx,
                        const float* __restrict__ wlat, int N, int E) {
    int e = blockIdx.x * blockDim.x + threadIdx.x;
    if (e >= E) return;
    int t = ei[E + e];
    int s = ei[e];
    int p = atomicAdd(&g_cursor[t], 1);
    float4 v;
    v.x = asp[e]  * wsp[e];
    v.y = actx[e] * wctx[e];
    v.z = alat[e] * wlat[e];
    v.w = __int_as_float(s);
    g_eff4[p] = v;
}

// ---------------- fused aux: [0, dd_blocks) = degrees+dinv4 ; rest = prep x/weights ----------------
__global__ void k_aux(const float* __restrict__ deg_power,
                      const float* __restrict__ x,
                      const float* __restrict__ Wself, const float* __restrict__ W3,
                      int L, int N, int dd_blocks) {
    if ((int)blockIdx.x < dd_blocks) {
        // degrees + dinv4; warp per node
        int gw = (blockIdx.x * blockDim.x + threadIdx.x) >> 5;
        int lane = threadIdx.x & 31;
        if (gw >= N) return;
        int s = g_rowstart[gw], e = g_rowstart[gw + 1];
        float d0 = 0.f, d1 = 0.f, d2 = 0.f;
        for (int p = s + lane; p < e; p += 32) {
            float4 v = __ldg(&g_eff4[p]);
            d0 += v.x; d1 += v.y; d2 += v.z;
        }
        #pragma unroll
        for (int o = 16; o > 0; o >>= 1) {
            d0 += __shfl_xor_sync(0xffffffffu, d0, o);
            d1 += __shfl_xor_sync(0xffffffffu, d1, o);
            d2 += __shfl_xor_sync(0xffffffffu, d2, o);
        }
        if (lane == 0) {
            float deg0 = fmaxf(1.f + d0, 1e-6f);
            float deg1 = fmaxf(1.f + d1, 1e-6f);
            float deg2 = fmaxf(1.f + d2, 1e-6f);
            for (int l = 0; l < L; l++) {
                float4 o;
                o.x = powf(deg0, __ldg(&deg_power[l * 3 + 0]));
                o.y = powf(deg1, __ldg(&deg_power[l * 3 + 1]));
                o.z = powf(deg2, __ldg(&deg_power[l * 3 + 2]));
                o.w = 0.f;
                g_dinv4[l * MAXN + gw] = o;
            }
        }
    } else {
        int idx = (blockIdx.x - dd_blocks) * blockDim.x + threadIdx.x;
        int nX = N * (D / 4);
        if (idx < nX) {
            float4 v = __ldg((const float4*)x + idx);
            uint4 t;
            t.x = f2tf32(v.x); t.y = f2tf32(v.y);
            t.z = f2tf32(v.z); t.w = f2tf32(v.w);
            *(uint4*)((uint32_t*)g_act0 + (size_t)idx * 4) = t;
        } else {
            int j = idx - nX;
            if (j >= L * 4 * D * D) return;
            int l  = j / (4 * D * D);
            int r  = j % (4 * D * D);
            int c  = r / (D * D);
            int nk = r % (D * D);
            int n  = nk >> 7;
            int k  = nk & 127;
            float v = (c == 0) ? Wself[l * D * D + k * D + n]
                               : W3[((l * 3) + (c - 1)) * D * D + k * D + n];
            ((uint32_t*)g_Bt)[j] = f2tf32(v);
        }
    }
}

// ---------------- aggregate: ONE WARP per target node (R12 shape) ----------------
__global__ void __launch_bounds__(256)
k_agg(const float* __restrict__ x, int use_h, int layer, int N) {
    int gw = (blockIdx.x * blockDim.x + threadIdx.x) >> 5;
    int lane = threadIdx.x & 31;
    if (gw >= N) return;
    const float* __restrict__ X = use_h ? g_act0 : x;
    const float4* __restrict__ dinv = g_dinv4 + layer * MAXN;
    int s = g_rowstart[gw];
    int e = g_rowstart[gw + 1];
    int fo = lane * 4;

    float4 a0 = make_float4(0.f, 0.f, 0.f, 0.f);
    float4 a1 = make_float4(0.f, 0.f, 0.f, 0.f);
    float4 a2 = make_float4(0.f, 0.f, 0.f, 0.f);

    int p = s;
    for (; p + 4 <= e; p += 4) {
        float4 e0 = __ldg(&g_eff4[p]);
        float4 e1 = __ldg(&g_eff4[p + 1]);
        float4 e2 = __ldg(&g_eff4[p + 2]);
        float4 e3 = __ldg(&g_eff4[p + 3]);
        int s0 = __float_as_int(e0.w);
        int s1 = __float_as_int(e1.w);
        int s2 = __float_as_int(e2.w);
        int s3 = __float_as_int(e3.w);
        float4 d0 = __ldg(&dinv[s0]);
        float4 d1 = __ldg(&dinv[s1]);
        float4 d2 = __ldg(&dinv[s2]);
        float4 d3 = __ldg(&dinv[s3]);
        float4 x0 = __ldg((const float4*)(X + (size_t)s0 * D + fo));
        float4 x1 = __ldg((const float4*)(X + (size_t)s1 * D + fo));
        float4 x2 = __ldg((const float4*)(X + (size_t)s2 * D + fo));
        float4 x3 = __ldg((const float4*)(X + (size_t)s3 * D + fo));
        float m;
        m = e0.x * d0.x; a0.x = fmaf(m, x0.x, a0.x); a0.y = fmaf(m, x0.y, a0.y); a0.z = fmaf(m, x0.z, a0.z); a0.w = fmaf(m, x0.w, a0.w);
        m = e0.y * d0.y; a1.x = fmaf(m, x0.x, a1.x); a1.y = fmaf(m, x0.y, a1.y); a1.z = fmaf(m, x0.z, a1.z); a1.w = fmaf(m, x0.w, a1.w);
        m = e0.z * d0.z; a2.x = fmaf(m, x0.x, a2.x); a2.y = fmaf(m, x0.y, a2.y); a2.z = fmaf(m, x0.z, a2.z); a2.w = fmaf(m, x0.w, a2.w);
        m = e1.x * d1.x; a0.x = fmaf(m, x1.x, a0.x); a0.y = fmaf(m, x1.y, a0.y); a0.z = fmaf(m, x1.z, a0.z); a0.w = fmaf(m, x1.w, a0.w);
        m = e1.y * d1.y; a1.x = fmaf(m, x1.x, a1.x); a1.y = fmaf(m, x1.y, a1.y); a1.z = fmaf(m, x1.z, a1.z); a1.w = fmaf(m, x1.w, a1.w);
        m = e1.z * d1.z; a2.x = fmaf(m, x1.x, a2.x); a2.y = fmaf(m, x1.y, a2.y); a2.z = fmaf(m, x1.z, a2.z); a2.w = fmaf(m, x1.w, a2.w);
        m = e2.x * d2.x; a0.x = fmaf(m, x2.x, a0.x); a0.y = fmaf(m, x2.y, a0.y); a0.z = fmaf(m, x2.z, a0.z); a0.w = fmaf(m, x2.w, a0.w);
        m = e2.y * d2.y; a1.x = fmaf(m, x2.x, a1.x); a1.y = fmaf(m, x2.y, a1.y); a1.z = fmaf(m, x2.z, a1.z); a1.w = fmaf(m, x2.w, a1.w);
        m = e2.z * d2.z; a2.x = fmaf(m, x2.x, a2.x); a2.y = fmaf(m, x2.y, a2.y); a2.z = fmaf(m, x2.z, a2.z); a2.w = fmaf(m, x2.w, a2.w);
        m = e3.x * d3.x; a0.x = fmaf(m, x3.x, a0.x); a0.y = fmaf(m, x3.y, a0.y); a0.z = fmaf(m, x3.z, a0.z); a0.w = fmaf(m, x3.w, a0.w);
        m = e3.y * d3.y; a1.x = fmaf(m, x3.x, a1.x); a1.y = fmaf(m, x3.y, a1.y); a1.z = fmaf(m, x3.z, a1.z); a1.w = fmaf(m, x3.w, a1.w);
        m = e3.z * d3.z; a2.x = fmaf(m, x3.x, a2.x); a2.y = fmaf(m, x3.y, a2.y); a2.z = fmaf(m, x3.z, a2.z); a2.w = fmaf(m, x3.w, a2.w);
    }
    for (; p < e; p++) {
        float4 ef = __ldg(&g_eff4[p]);
        int sid = __float_as_int(ef.w);
        float4 dv = __ldg(&dinv[sid]);
        float4 xv = __ldg((const float4*)(X + (size_t)sid * D + fo));
        float m0 = ef.x * dv.x, m1 = ef.y * dv.y, m2 = ef.z * dv.z;
        a0.x = fmaf(m0, xv.x, a0.x); a0.y = fmaf(m0, xv.y, a0.y); a0.z = fmaf(m0, xv.z, a0.z); a0.w = fmaf(m0, xv.w, a0.w);
        a1.x = fmaf(m1, xv.x, a1.x); a1.y = fmaf(m1, xv.y, a1.y); a1.z = fmaf(m1, xv.z, a1.z); a1.w = fmaf(m1, xv.w, a1.w);
        a2.x = fmaf(m2, xv.x, a2.x); a2.y = fmaf(m2, xv.y, a2.y); a2.z = fmaf(m2, xv.z, a2.z); a2.w = fmaf(m2, xv.w, a2.w);
    }

    float4 dt = dinv[gw];
    uint4 t;
    t.x = f2tf32(a0.x * dt.x); t.y = f2tf32(a0.y * dt.x);
    t.z = f2tf32(a0.z * dt.x); t.w = f2tf32(a0.w * dt.x);
    *(uint4*)((uint32_t*)g_agg + (size_t)gw * D + fo) = t;
    t.x = f2tf32(a1.x * dt.y); t.y = f2tf32(a1.y * dt.y);
    t.z = f2tf32(a1.z * dt.y); t.w = f2tf32(a1.w * dt.y);
    *(uint4*)((uint32_t*)g_agg + (size_t)MAXN * D + (size_t)gw * D + fo) = t;
    t.x = f2tf32(a2.x * dt.z); t.y = f2tf32(a2.y * dt.z);
    t.z = f2tf32(a2.z * dt.z); t.w = f2tf32(a2.w * dt.z);
    *(uint4*)((uint32_t*)g_agg + 2 * (size_t)MAXN * D + (size_t)gw * D + fo) = t;
}

// ---------------- TF32 GEMM with cp.async double-buffered staging + fused LN ----------------
constexpr int PP = 36;
constexpr int ABYTES = 128 * PP * 4;
constexpr int BUFB = 2 * ABYTES;
constexpr int SMEM_GEMM = 2 * BUFB;               // 73728

__device__ __forceinline__ void cp16(uint32_t dst, const void* src) {
    asm volatile("cp.async.cg.shared.global [%0], [%1], 16;" :: "r"(dst), "l"(src));
}
__device__ __forceinline__ void cp_commit() {
    asm volatile("cp.async.commit_group;" ::: "memory");
}
__device__ __forceinline__ void cp_wait1() {
    asm volatile("cp.async.wait_group 1;" ::: "memory");
}
__device__ __forceinline__ void cp_wait0() {
    asm volatile("cp.async.wait_group 0;" ::: "memory");
}

__device__ __forceinline__ void mma_tf32(float* d, const uint32_t* a, const uint32_t* b) {
    asm volatile("mma.sync.aligned.m16n8k8.row.col.f32.tf32.tf32.f32 "
        "{%0,%1,%2,%3}, {%4,%5,%6,%7}, {%8,%9}, {%0,%1,%2,%3};"
        : "+f"(d[0]), "+f"(d[1]), "+f"(d[2]), "+f"(d[3])
        : "r"(a[0]), "r"(a[1]), "r"(a[2]), "r"(a[3]), "r"(b[0]), "r"(b[1]));
}

__global__ void __launch_bounds__(256, 2)
k_gemm_mma(int layer, const float* __restrict__ bias,
           const float* __restrict__ lng, const float* __restrict__ lnb,
           float* __restrict__ dout, int last, int N) {
    extern __shared__ char smem[];
    uint32_t sbase = (uint32_t)__cvta_generic_to_shared(smem);

    int tid = threadIdx.x;
    int wid = tid >> 5;
    int lane = tid & 31;
    int group = lane >> 2;
    int tg = lane & 3;
    int warp_m = wid >> 2;
    int warp_n = wid & 3;
    int bm0 = blockIdx.x * 128;

    const uint32_t* BtL = (const uint32_t*)g_Bt + (size_t)layer * 4 * D * D;

    float acc[4][4][4];
    #pragma unroll
    for (int mt = 0; mt < 4; mt++)
        #pragma unroll
        for (int nt = 0; nt < 4; nt++)
            #pragma unroll
            for (int j = 0; j < 4; j++) acc[mt][nt][j] = 0.f;

    auto stage = [&](int chunk, int b) {
        int c = chunk >> 2;
        int koff = (chunk & 3) * 32;
        const float* Asrc = (c == 0) ? g_act0 : (g_agg + (size_t)(c - 1) * MAXN * D);
        const uint32_t* bsrc = BtL + c * D * D + koff;
        uint32_t a_s = sbase + b * BUFB;
        uint32_t b_s = a_s + ABYTES;
        #pragma unroll
        for (int i = 0; i < 4; i++) {
            int u = tid + i * 256;
            int row = u >> 3;
            int q = u & 7;
            cp16(a_s + (uint32_t)(row * PP + q * 4) * 4,
                 Asrc + (size_t)(bm0 + row) * D + koff + q * 4);
            cp16(b_s + (uint32_t)(row * PP + q * 4) * 4,
                 bsrc + (size_t)row * D + q * 4);
        }
    };

    stage(0, 0);
    cp_commit();

    for (int ch = 0; ch < 16; ch++) {
        if (ch < 15) {
            stage(ch + 1, (ch + 1) & 1);
            cp_commit();
            cp_wait1();
        } else {
            cp_wait0();
        }
        __syncthreads();

        const uint32_t* As = (const uint32_t*)(smem + (ch & 1) * BUFB);
        const uint32_t* Bs = (const uint32_t*)(smem + (ch & 1) * BUFB + ABYTES);

        #pragma unroll
        for (int s = 0; s < 4; s++) {
            int ks = s * 8;
            uint32_t bf[4][2];
            #pragma unroll
            for (int nt = 0; nt < 4; nt++) {
                int n0 = warp_n * 32 + nt * 8 + group;
                int o = n0 * PP + ks + tg;
                bf[nt][0] = Bs[o];
                bf[nt][1] = Bs[o + 4];
            }
            #pragma unroll
            for (int mt = 0; mt < 4; mt++) {
                int r0 = warp_m * 64 + mt * 16 + group;
                int o = r0 * PP + ks + tg;
                uint32_t af[4];
                af[0] = As[o];
                af[1] = As[o + 8 * PP];
                af[2] = As[o + 4];
                af[3] = As[o + 8 * PP + 4];
                #pragma unroll
                for (int nt = 0; nt < 4; nt++)
                    mma_tf32(acc[mt][nt], af, bf[nt]);
            }
        }
        __syncthreads();
    }

    // ---- add bias ----
    #pragma unroll
    for (int mt = 0; mt < 4; mt++)
        #pragma unroll
        for (int nt = 0; nt < 4; nt++) {
            int c0 = warp_n * 32 + nt * 8 + tg * 2;
            float b0 = bias[c0], b1 = bias[c0 + 1];
            acc[mt][nt][0] += b0; acc[mt][nt][1] += b1;
            acc[mt][nt][2] += b0; acc[mt][nt][3] += b1;
        }

    if (last) {
        #pragma unroll
        for (int mt = 0; mt < 4; mt++) {
            int r0 = bm0 + warp_m * 64 + mt * 16 + group;
            #pragma unroll
            for (int nt = 0; nt < 4; nt++) {
                int c0 = warp_n * 32 + nt * 8 + tg * 2;
                if (r0 < N)
                    *(float2*)(dout + (size_t)r0 * D + c0) = make_float2(acc[mt][nt][0], acc[mt][nt][1]);
                if (r0 + 8 < N)
                    *(float2*)(dout + (size_t)(r0 + 8) * D + c0) = make_float2(acc[mt][nt][2], acc[mt][nt][3]);
            }
        }
        return;
    }

    // ---- fused LayerNorm + ReLU -> tf32-rounded g_act0 (reuses staging smem) ----
    float* rsum = (float*)smem;
    float* rsq  = rsum + 512;

    #pragma unroll
    for (int mt = 0; mt < 4; mt++) {
        float slo = 0.f, shi = 0.f, qlo = 0.f, qhi = 0.f;
        #pragma unroll
        for (int nt = 0; nt < 4; nt++) {
            slo += acc[mt][nt][0] + acc[mt][nt][1];
            shi += acc[mt][nt][2] + acc[mt][nt][3];
            qlo += acc[mt][nt][0] * acc[mt][nt][0] + acc[mt][nt][1] * acc[mt][nt][1];
            qhi += acc[mt][nt][2] * acc[mt][nt][2] + acc[mt][nt][3] * acc[mt][nt][3];
        }
        #pragma unroll
        for (int o = 1; o < 4; o <<= 1) {
            slo += __shfl_xor_sync(0xffffffffu, slo, o);
            shi += __shfl_xor_sync(0xffffffffu, shi, o);
            qlo += __shfl_xor_sync(0xffffffffu, qlo, o);
            qhi += __shfl_xor_sync(0xffffffffu, qhi, o);
        }
        if (tg == 0) {
            int rl = warp_m * 64 + mt * 16 + group;
            rsum[rl * 4 + warp_n] = slo;
            rsq [rl * 4 + warp_n] = qlo;
            rsum[(rl + 8) * 4 + warp_n] = shi;
            rsq [(rl + 8) * 4 + warp_n] = qhi;
        }
    }
    __syncthreads();

    #pragma unroll
    for (int mt = 0; mt < 4; mt++) {
        int rl = warp_m * 64 + mt * 16 + group;
        float s0 = rsum[rl * 4 + 0] + rsum[rl * 4 + 1] + rsum[rl * 4 + 2] + rsum[rl * 4 + 3];
        float q0 = rsq [rl * 4 + 0] + rsq [rl * 4 + 1] + rsq [rl * 4 + 2] + rsq [rl * 4 + 3];
        float s1 = rsum[(rl + 8) * 4 + 0] + rsum[(rl + 8) * 4 + 1] + rsum[(rl + 8) * 4 + 2] + rsum[(rl + 8) * 4 + 3];
        float q1 = rsq [(rl + 8) * 4 + 0] + rsq [(rl + 8) * 4 + 1] + rsq [(rl + 8) * 4 + 2] + rsq [(rl + 8) * 4 + 3];
        float mu0 = s0 * (1.0f / 128.0f);
        float mu1 = s1 * (1.0f / 128.0f);
        float rs0 = rsqrtf(q0 * (1.0f / 128.0f) - mu0 * mu0 + 1e-5f);
        float rs1 = rsqrtf(q1 * (1.0f / 128.0f) - mu1 * mu1 + 1e-5f);
        int r0 = bm0 + rl;
        #pragma unroll
        for (int nt = 0; nt < 4; nt++) {
            int c0 = warp_n * 32 + nt * 8 + tg * 2;
            float gc0 = lng[c0], gc1 = lng[c0 + 1];
            float bc0 = lnb[c0], bc1 = lnb[c0 + 1];
            float y00 = fmaxf((acc[mt][nt][0] - mu0) * rs0 * gc0 + bc0, 0.f);
            float y01 = fmaxf((acc[mt][nt][1] - mu0) * rs0 * gc1 + bc1, 0.f);
            float y10 = fmaxf((acc[mt][nt][2] - mu1) * rs1 * gc0 + bc0, 0.f);
            float y11 = fmaxf((acc[mt][nt][3] - mu1) * rs1 * gc1 + bc1, 0.f);
            if (r0 < N) {
                uint2 t = make_uint2(f2tf32(y00), f2tf32(y01));
                *(uint2*)((uint32_t*)g_act0 + (size_t)r0 * D + c0) = t;
            }
            if (r0 + 8 < N) {
                uint2 t = make_uint2(f2tf32(y10), f2tf32(y11));
                *(uint2*)((uint32_t*)g_act0 + (size_t)(r0 + 8) * D + c0) = t;
            }
        }
    }
}

// ---------------- launch ----------------
extern "C" void kernel_launch(void* const* d_in, const int* in_sizes, int n_in,
                              void* d_out, int out_size) {
    const float* x    = (const float*)d_in[0];
    const int*   ei   = (const int*)d_in[1];
    const float* asp  = (const float*)d_in[2];
    const float* actx = (const float*)d_in[3];
    const float* alat = (const float*)d_in[4];
    const float* wsp  = (const float*)d_in[5];
    const float* wctx = (const float*)d_in[6];
    const float* wlat = (const float*)d_in[7];
    const float* W3   = (const float*)d_in[8];   // [L,3,D,D]
    const float* Wslf = (const float*)d_in[9];   // [L,D,D]
    const float* bias = (const float*)d_in[10];  // [L,D]
    const float* degp = (const float*)d_in[11];  // [L,3]
    const float* lng  = (const float*)d_in[12];
    const float* lnb  = (const float*)d_in[13];
    float* out = (float*)d_out;

    int N = in_sizes[0] / D;
    int E = in_sizes[2];
    int L = in_sizes[10] / D;
    int nblk = (N + 255) / 256;

    cudaFuncSetAttribute(k_gemm_mma, cudaFuncAttributeMaxDynamicSharedMemorySize, SMEM_GEMM);

    k_init<<<(N + 255) / 256, 256>>>(N);
    k_edge1<<<((E + 3) / 4 + 255) / 256, 256>>>(ei, N, E);
    k_scan1<<<nblk, 256>>>(N);
    k_scan3<<<nblk, 256>>>(N, E);
    k_edge2<<<(E + 255) / 256, 256>>>(ei, asp, actx, alat, wsp, wctx, wlat, N, E);

    int dd_blocks = (N * 32 + 255) / 256;
    int prep_total = N * (D / 4) + L * 4 * D * D;
    int prep_blocks = (prep_total + 255) / 256;
    k_aux<<<dd_blocks + prep_blocks, 256>>>(degp, x, Wslf, W3, L, N, dd_blocks);

    int gemm_grid = (N + 127) / 128;
    for (int l = 0; l < L; l++) {
        int use_h = (l > 0) ? 1 : 0;
        int last = (l == L - 1) ? 1 : 0;
        k_agg<<<(N * 32 + 255) / 256, 256>>>(x, use_h, l, N);
        k_gemm_mma<<<gemm_grid, 256, SMEM_GEMM>>>(l, bias + l * D, lng, lnb, out, last, N);
    }
}